// round 16
// baseline (speedup 1.0000x reference)
#include <cuda_runtime.h>
#include <cuda_bf16.h>
#include <math.h>
#include <stdint.h>

#define NB 8
#define NT 1221
#define NC 1024
#define NH 16
#define ND 64
#define NM (NB*NT)      // 9768
#define HV 6
#define VTS 12
#define VTP 1280        // padded T for V^T layout (zero padding, 16B aligned rows)

#define BM 128
#define BN 128
#define KTILE 32
#define NKT (NC/KTILE)  // 32
#define PITCH 40        // GEMM smem pitch (bf16) -> conflict-free ldmatrix
#define APITCH 72       // attn smem pitch (bf16) -> conflict-free ldmatrix
#define ASEG (64*APITCH)

// ---------------- scratch (device globals; no allocation allowed) ------------
__device__ float g_cs[NT*32];
__device__ float g_sn[NT*32];
__device__ __nv_bfloat16 g_xh[(size_t)NM*NC];   // A operand hi (X, later attn-out)
__device__ __nv_bfloat16 g_xl[(size_t)NM*NC];   // A operand lo
__device__ __nv_bfloat16 g_wh[4*(size_t)NC*NC]; // Wq,Wk,Wv,Wo hi
__device__ __nv_bfloat16 g_wl[4*(size_t)NC*NC]; // lo
__device__ __nv_bfloat16 g_qh[(size_t)NB*NH*NT*ND];  // Q hi [B,H,T,D]
__device__ __nv_bfloat16 g_ql[(size_t)NB*NH*NT*ND];
__device__ __nv_bfloat16 g_kh[(size_t)NB*NH*NT*ND];  // K hi [B,H,T,D]
__device__ __nv_bfloat16 g_kl[(size_t)NB*NH*NT*ND];
__device__ __nv_bfloat16 g_vth[(size_t)NB*NH*ND*VTP]; // V^T hi [B,H,D,VTP] (pad=0)
__device__ __nv_bfloat16 g_vtl[(size_t)NB*NH*ND*VTP];

// ---------------- helpers ----------------------------------------------------
__device__ __forceinline__ void mma16(float* d,
                                      uint32_t a0, uint32_t a1, uint32_t a2, uint32_t a3,
                                      uint32_t b0, uint32_t b1) {
    asm volatile(
        "mma.sync.aligned.m16n8k16.row.col.f32.bf16.bf16.f32 "
        "{%0,%1,%2,%3},{%4,%5,%6,%7},{%8,%9},{%0,%1,%2,%3};\n"
        : "+f"(d[0]), "+f"(d[1]), "+f"(d[2]), "+f"(d[3])
        : "r"(a0), "r"(a1), "r"(a2), "r"(a3), "r"(b0), "r"(b1));
}
__device__ __forceinline__ void ldsm4(uint32_t& r0, uint32_t& r1, uint32_t& r2, uint32_t& r3,
                                      uint32_t addr) {
    asm volatile("ldmatrix.sync.aligned.m8n8.x4.shared.b16 {%0,%1,%2,%3}, [%4];"
                 : "=r"(r0), "=r"(r1), "=r"(r2), "=r"(r3) : "r"(addr));
}
__device__ __forceinline__ void cpa16(__nv_bfloat16* dst, const __nv_bfloat16* src, bool pred) {
    uint32_t d = (uint32_t)__cvta_generic_to_shared(dst);
    int sz = pred ? 16 : 0;
    asm volatile("cp.async.cg.shared.global [%0], [%1], 16, %2;\n"
                 :: "r"(d), "l"(src), "r"(sz));
}
#define CP_COMMIT() asm volatile("cp.async.commit_group;\n")

__device__ __forceinline__ void bf_split(float x, __nv_bfloat16& h, __nv_bfloat16& l) {
    h = __float2bfloat16(x);
    l = __float2bfloat16(x - __bfloat162float(h));
}
__device__ __forceinline__ uint32_t us2(__nv_bfloat16 a, __nv_bfloat16 b) {
    return (uint32_t)__bfloat16_as_ushort(a) | ((uint32_t)__bfloat16_as_ushort(b) << 16);
}

// GEMM smem layout (bf16 elements)
#define A_ELE (BM*PITCH)
#define B_ELE (BN*PITCH)
#define STAGE_ELE (2*A_ELE + 2*B_ELE)
#define AH_E(s) ((s)*STAGE_ELE)
#define AL_E(s) (AH_E(s) + A_ELE)
#define BH_E(s) (AH_E(s) + 2*A_ELE)
#define BL_E(s) (AH_E(s) + 2*A_ELE + B_ELE)
#define SMEM_GEMM (2*STAGE_ELE*2)   // 81920 B

// attn smem: Qh, Ql, then 2 stages x {Kh, Kl, Vh, Vl}
#define SMEM_ATTN (10*ASEG*2)       // 92160 B

// ---------------- rope table -------------------------------------------------
__global__ void cis_kernel() {
    int idx = blockIdx.x*256 + threadIdx.x;
    if (idx >= NT*32) return;
    int t = idx >> 5;
    int i = idx & 31;
    float inv = powf(10000.0f, -((float)(2*i) / 64.0f));
    float ang = (float)t * inv;
    float s, c;
    sincosf(ang, &s, &c);
    g_cs[idx] = c;
    g_sn[idx] = s;
}

// ---------------- fp32 -> (bf16 hi, bf16 lo) conversion ----------------------
__global__ __launch_bounds__(256) void cvt_kernel(
    const float* __restrict__ x,  const float* __restrict__ wq,
    const float* __restrict__ wk, const float* __restrict__ wv,
    const float* __restrict__ wo)
{
    const int seg = blockIdx.y;
    const float* src;
    __nv_bfloat16 *hi, *lo;
    size_t n;
    if (seg == 0) { src = x;  hi = g_xh; lo = g_xl; n = (size_t)NM*NC; }
    else {
        src = (seg==1) ? wq : (seg==2) ? wk : (seg==3) ? wv : wo;
        hi = g_wh + (size_t)(seg-1)*NC*NC;
        lo = g_wl + (size_t)(seg-1)*NC*NC;
        n = (size_t)NC*NC;
    }
    size_t i = ((size_t)blockIdx.x*256 + threadIdx.x) * 4;
    if (i >= n) return;
    float4 v = *(const float4*)(src + i);
    __nv_bfloat16 h0, l0, h1, l1, h2, l2, h3, l3;
    bf_split(v.x, h0, l0); bf_split(v.y, h1, l1);
    bf_split(v.z, h2, l2); bf_split(v.w, h3, l3);
    uint2 hp, lp;
    hp.x = us2(h0, h1); hp.y = us2(h2, h3);
    lp.x = us2(l0, l1); lp.y = us2(l2, l3);
    *(uint2*)(hi + i) = hp;
    *(uint2*)(lo + i) = lp;
}

// ---------------- 3-pass bf16-split GEMM mainloop (mma + ldmatrix) -----------
// 128 threads, 4 warps in 2x2 grid, warp tile 64x64 (6:1 mma:ldsm).
__device__ __forceinline__ void gemm_main(
    const __nv_bfloat16* __restrict__ Ah, const __nv_bfloat16* __restrict__ Al,
    const __nv_bfloat16* __restrict__ Bh, const __nv_bfloat16* __restrict__ Bl,
    int m0, int n0, __nv_bfloat16* sm, float acc[4][8][4])
{
    const int tid  = threadIdx.x;
    const int lane = tid & 31;
    const int warp = tid >> 5;
    const int wm = (warp >> 1) * 64;
    const int wn = (warp & 1) * 64;

    const int lrowA = (lane & 7) + ((lane >> 3) & 1) * 8;
    const int lcolA = ((lane >> 4) & 1) * 8;
    const int lrowB = (lane & 7) + ((lane >> 4) & 1) * 8;
    const int lcolB = ((lane >> 3) & 1) * 8;

    const uint32_t sb = (uint32_t)__cvta_generic_to_shared(sm);

    const bool pa = (m0 + tid) < NM;
    const __nv_bfloat16* arh = Ah + (size_t)(m0 + tid) * NC;
    const __nv_bfloat16* arl = Al + (size_t)(m0 + tid) * NC;
    const __nv_bfloat16* brh = Bh + (size_t)(n0 + tid) * NC;
    const __nv_bfloat16* brl = Bl + (size_t)(n0 + tid) * NC;

    {
        __nv_bfloat16* dah = sm + AH_E(0) + tid*PITCH;
        __nv_bfloat16* dal = sm + AL_E(0) + tid*PITCH;
        __nv_bfloat16* dbh = sm + BH_E(0) + tid*PITCH;
        __nv_bfloat16* dbl = sm + BL_E(0) + tid*PITCH;
        #pragma unroll
        for (int c = 0; c < 4; c++) {
            cpa16(dah + c*8, arh + c*8, pa);
            cpa16(dal + c*8, arl + c*8, pa);
            cpa16(dbh + c*8, brh + c*8, true);
            cpa16(dbl + c*8, brl + c*8, true);
        }
        CP_COMMIT();
    }

    for (int kt = 0; kt < NKT; kt++) {
        const int buf = kt & 1;
        if (kt + 1 < NKT) {
            const int k0n = (kt + 1) * KTILE;
            const int s2 = buf ^ 1;
            __nv_bfloat16* dah = sm + AH_E(s2) + tid*PITCH;
            __nv_bfloat16* dal = sm + AL_E(s2) + tid*PITCH;
            __nv_bfloat16* dbh = sm + BH_E(s2) + tid*PITCH;
            __nv_bfloat16* dbl = sm + BL_E(s2) + tid*PITCH;
            #pragma unroll
            for (int c = 0; c < 4; c++) {
                cpa16(dah + c*8, arh + k0n + c*8, pa);
                cpa16(dal + c*8, arl + k0n + c*8, pa);
                cpa16(dbh + c*8, brh + k0n + c*8, true);
                cpa16(dbl + c*8, brl + k0n + c*8, true);
            }
            CP_COMMIT();
            asm volatile("cp.async.wait_group 1;\n" ::: "memory");
        } else {
            asm volatile("cp.async.wait_group 0;\n" ::: "memory");
        }
        __syncthreads();

        const uint32_t aBh = sb + (uint32_t)(AH_E(buf) + (wm + lrowA)*PITCH + lcolA)*2;
        const uint32_t aBl = sb + (uint32_t)(AL_E(buf) + (wm + lrowA)*PITCH + lcolA)*2;
        const uint32_t bBh = sb + (uint32_t)(BH_E(buf) + (wn + lrowB)*PITCH + lcolB)*2;
        const uint32_t bBl = sb + (uint32_t)(BL_E(buf) + (wn + lrowB)*PITCH + lcolB)*2;

        #pragma unroll
        for (int ks = 0; ks < 2; ks++) {
            const uint32_t ko = (uint32_t)(ks*16*2);
            uint32_t ah[4][4], al[4][4], bh[8][2], bl[8][2];
            #pragma unroll
            for (int mi = 0; mi < 4; mi++) {
                ldsm4(ah[mi][0], ah[mi][1], ah[mi][2], ah[mi][3],
                      aBh + (uint32_t)(mi*16*PITCH*2) + ko);
                ldsm4(al[mi][0], al[mi][1], al[mi][2], al[mi][3],
                      aBl + (uint32_t)(mi*16*PITCH*2) + ko);
            }
            #pragma unroll
            for (int np = 0; np < 4; np++) {
                ldsm4(bh[2*np][0], bh[2*np][1], bh[2*np+1][0], bh[2*np+1][1],
                      bBh + (uint32_t)(np*16*PITCH*2) + ko);
                ldsm4(bl[2*np][0], bl[2*np][1], bl[2*np+1][0], bl[2*np+1][1],
                      bBl + (uint32_t)(np*16*PITCH*2) + ko);
            }
            #pragma unroll
            for (int mi = 0; mi < 4; mi++)
                #pragma unroll
                for (int ni = 0; ni < 8; ni++)
                    mma16(acc[mi][ni], ah[mi][0], ah[mi][1], ah[mi][2], ah[mi][3],
                          bh[ni][0], bh[ni][1]);
            #pragma unroll
            for (int mi = 0; mi < 4; mi++)
                #pragma unroll
                for (int ni = 0; ni < 8; ni++)
                    mma16(acc[mi][ni], al[mi][0], al[mi][1], al[mi][2], al[mi][3],
                          bh[ni][0], bh[ni][1]);
            #pragma unroll
            for (int mi = 0; mi < 4; mi++)
                #pragma unroll
                for (int ni = 0; ni < 8; ni++)
                    mma16(acc[mi][ni], ah[mi][0], ah[mi][1], ah[mi][2], ah[mi][3],
                          bl[ni][0], bl[ni][1]);
        }
        __syncthreads();
    }
}

// ---------------- fused QKV GEMM + RoPE + bf16 hi/lo outputs -----------------
__global__ __launch_bounds__(128, 2) void qkv_kernel()
{
    extern __shared__ __nv_bfloat16 sm[];
    const int which = blockIdx.z;
    const __nv_bfloat16* Bh = g_wh + (size_t)which*NC*NC;
    const __nv_bfloat16* Bl = g_wl + (size_t)which*NC*NC;

    const int m0 = blockIdx.y * BM;
    const int n0 = blockIdx.x * BN;

    float acc[4][8][4];
    #pragma unroll
    for (int mi = 0; mi < 4; mi++)
        #pragma unroll
        for (int ni = 0; ni < 8; ni++)
            #pragma unroll
            for (int j = 0; j < 4; j++) acc[mi][ni][j] = 0.f;

    gemm_main(g_xh, g_xl, Bh, Bl, m0, n0, sm, acc);

    const int tid  = threadIdx.x;
    const int lane = tid & 31;
    const int warp = tid >> 5;
    const int wm = (warp >> 1) * 64;
    const int wn = (warp & 1) * 64;
    const int g = lane >> 2;
    const int t = lane & 3;

    #pragma unroll
    for (int mi = 0; mi < 4; mi++) {
        #pragma unroll
        for (int half = 0; half < 2; half++) {
            const int m = m0 + wm + mi*16 + g + half*8;
            if (m >= NM) continue;
            const int bb  = m / NT;
            const int tok = m - bb*NT;
            #pragma unroll
            for (int ni = 0; ni < 8; ni++) {
                const int n = n0 + wn + ni*8 + 2*t;
                const int hh = n >> 6, d = n & 63;
                float e = acc[mi][ni][half*2 + 0];
                float o = acc[mi][ni][half*2 + 1];
                if (which < 2) {
                    float cv = g_cs[tok*32 + (d >> 1)];
                    float sv = g_sn[tok*32 + (d >> 1)];
                    float oe = e*cv - o*sv;
                    float oo = e*sv + o*cv;
                    __nv_bfloat16 he, le, ho, lo2;
                    bf_split(oe, he, le);
                    bf_split(oo, ho, lo2);
                    size_t idx = ((size_t)(bb*NH + hh)*NT + tok)*ND + d;
                    if (which == 0) {
                        *(uint32_t*)&g_qh[idx] = us2(he, ho);
                        *(uint32_t*)&g_ql[idx] = us2(le, lo2);
                    } else {
                        *(uint32_t*)&g_kh[idx] = us2(he, ho);
                        *(uint32_t*)&g_kl[idx] = us2(le, lo2);
                    }
                } else {
                    __nv_bfloat16 he, le, ho, lo2;
                    bf_split(e, he, le);
                    bf_split(o, ho, lo2);
                    size_t rbase = (size_t)(bb*NH + hh)*ND;
                    g_vth[(rbase + d  )*VTP + tok] = he;
                    g_vth[(rbase + d+1)*VTP + tok] = ho;
                    g_vtl[(rbase + d  )*VTP + tok] = le;
                    g_vtl[(rbase + d+1)*VTP + tok] = lo2;
                }
            }
        }
    }
}

// ---------------- output projection: out = AO @ Wo^T + bo --------------------
__global__ __launch_bounds__(128, 2) void proj_kernel(
    const float* __restrict__ bias, float* __restrict__ out)
{
    extern __shared__ __nv_bfloat16 sm[];
    const __nv_bfloat16* Bh = g_wh + (size_t)3*NC*NC;
    const __nv_bfloat16* Bl = g_wl + (size_t)3*NC*NC;

    const int m0 = blockIdx.y * BM;
    const int n0 = blockIdx.x * BN;

    float acc[4][8][4];
    #pragma unroll
    for (int mi = 0; mi < 4; mi++)
        #pragma unroll
        for (int ni = 0; ni < 8; ni++)
            #pragma unroll
            for (int j = 0; j < 4; j++) acc[mi][ni][j] = 0.f;

    gemm_main(g_xh, g_xl, Bh, Bl, m0, n0, sm, acc);

    const int tid  = threadIdx.x;
    const int lane = tid & 31;
    const int warp = tid >> 5;
    const int wm = (warp >> 1) * 64;
    const int wn = (warp & 1) * 64;
    const int g = lane >> 2;
    const int t = lane & 3;

    #pragma unroll
    for (int mi = 0; mi < 4; mi++) {
        #pragma unroll
        for (int half = 0; half < 2; half++) {
            const int m = m0 + wm + mi*16 + g + half*8;
            if (m >= NM) continue;
            #pragma unroll
            for (int ni = 0; ni < 8; ni++) {
                const int n = n0 + wn + ni*8 + 2*t;
                float2 r = make_float2(acc[mi][ni][half*2 + 0] + bias[n],
                                       acc[mi][ni][half*2 + 1] + bias[n+1]);
                *(float2*)&out[(size_t)m*NC + n] = r;
            }
        }
    }
}

// ---------------- tensor-core flash attention with modality mask -------------
// K/V tiles double-buffered via cp.async (stage s holds Kh,Kl,Vh,Vl).
__global__ __launch_bounds__(128, 2) void attn_kernel(const int* __restrict__ svp)
{
    extern __shared__ __nv_bfloat16 smb[];
    __nv_bfloat16* sQh = smb;
    __nv_bfloat16* sQl = smb + ASEG;

    const int S_V = *svp;
    const int qt = blockIdx.x, h = blockIdx.y, b = blockIdx.z;
    const int hc = (h < HV) ? 0 : ((h < VTS) ? 1 : 2);
    const int q0 = qt * 64;
    const int tid = threadIdx.x, lane = tid & 31, w = tid >> 5;
    const int g = lane >> 2, t = lane & 3;
    const size_t bh = (size_t)(b*NH + h);

    const int lrowA = (lane & 7) + ((lane >> 3) & 1) * 8;
    const int lcolA = ((lane >> 4) & 1) * 8;
    const int lrowB = (lane & 7) + ((lane >> 4) & 1) * 8;
    const int lcolB = ((lane >> 3) & 1) * 8;

    const uint32_t sbQh = (uint32_t)__cvta_generic_to_shared(sQh);
    const uint32_t sbQl = (uint32_t)__cvta_generic_to_shared(sQl);
    const uint32_t sbS0 = (uint32_t)__cvta_generic_to_shared(smb + 2*ASEG);

    // loader indices (per thread: row r, half hf)
    const int r  = tid >> 1;
    const int hf = tid & 1;
    const __nv_bfloat16* gkh = g_kh + (bh*NT)*ND + hf*32;
    const __nv_bfloat16* gkl = g_kl + (bh*NT)*ND + hf*32;
    const __nv_bfloat16* gvh = g_vth + (bh*ND + r)*VTP + hf*32;
    const __nv_bfloat16* gvl = g_vtl + (bh*ND + r)*VTP + hf*32;

    // ---- load Q tile (hi/lo) ----
    {
        int q = q0 + r;
        uint4 z = make_uint4(0,0,0,0);
        const uint4* srh = (const uint4*)&g_qh[(bh*NT + (q < NT ? q : 0))*ND + hf*32];
        const uint4* srl = (const uint4*)&g_ql[(bh*NT + (q < NT ? q : 0))*ND + hf*32];
        #pragma unroll
        for (int i = 0; i < 4; i++) {
            uint4 vh_ = (q < NT) ? srh[i] : z;
            uint4 vl_ = (q < NT) ? srl[i] : z;
            *(uint4*)&sQh[r*APITCH + hf*32 + i*8] = vh_;
            *(uint4*)&sQl[r*APITCH + hf*32 + i*8] = vl_;
        }
    }
    __syncthreads();

    // ---- Q fragments (resident across KV loop) via ldmatrix ----
    uint32_t qfh[4][4], qfl[4][4];
    {
        const uint32_t qb = (uint32_t)(((w*16 + lrowA)*APITCH + lcolA)*2);
        #pragma unroll
        for (int ks = 0; ks < 4; ks++) {
            ldsm4(qfh[ks][0], qfh[ks][1], qfh[ks][2], qfh[ks][3], sbQh + qb + ks*32);
            ldsm4(qfl[ks][0], qfl[ks][1], qfl[ks][2], qfl[ks][3], sbQl + qb + ks*32);
        }
    }

    float O[8][4];
    #pragma unroll
    for (int ni = 0; ni < 8; ni++)
        #pragma unroll
        for (int c = 0; c < 4; c++) O[ni][c] = 0.f;
    float m_[2] = {-1e30f, -1e30f}, l_[2] = {0.f, 0.f};

    const int ceil_sv = (S_V + 63) >> 6;
    int kv_lo = 0, kv_hi = 0;
    if (hc == 0)      { if (q0 < S_V) { kv_lo = 0; kv_hi = ceil_sv; } }
    else if (hc == 1) { if (q0 + 63 >= S_V) { kv_lo = S_V >> 6; kv_hi = qt + 1; } }
    else              { kv_lo = 0; kv_hi = (qt + 1 > ceil_sv) ? (qt + 1) : ceil_sv; }

    const int qg = q0 + w*16 + g;
    const uint32_t kvb = (uint32_t)((lrowB*APITCH + lcolB)*2);

    // softmax in base-2 domain: scale includes log2(e)
    const float SC = 0.125f * 1.44269504088896f;

    if (kv_lo < kv_hi) {
        // prologue: stage 0 <- tile kv_lo
        {
            const int kv0 = kv_lo * 64;
            const int kv = kv0 + r;
            const bool pk = (kv < NT);
            __nv_bfloat16* base = smb + 2*ASEG;   // stage 0
            #pragma unroll
            for (int i = 0; i < 4; i++) {
                cpa16(base          + r*APITCH + hf*32 + i*8, gkh + (size_t)kv*ND + i*8, pk);
                cpa16(base +   ASEG + r*APITCH + hf*32 + i*8, gkl + (size_t)kv*ND + i*8, pk);
                cpa16(base + 2*ASEG + r*APITCH + hf*32 + i*8, gvh + kv0 + i*8, true);
                cpa16(base + 3*ASEG + r*APITCH + hf*32 + i*8, gvl + kv0 + i*8, true);
            }
            CP_COMMIT();
        }

        for (int kvt = kv_lo; kvt < kv_hi; kvt++) {
            const int s = (kvt - kv_lo) & 1;
            if (kvt + 1 < kv_hi) {
                const int kv0n = (kvt + 1) * 64;
                const int kvn = kv0n + r;
                const bool pk = (kvn < NT);
                __nv_bfloat16* base = smb + 2*ASEG + (size_t)(s^1)*4*ASEG;
                #pragma unroll
                for (int i = 0; i < 4; i++) {
                    cpa16(base          + r*APITCH + hf*32 + i*8, gkh + (size_t)kvn*ND + i*8, pk);
                    cpa16(base +   ASEG + r*APITCH + hf*32 + i*8, gkl + (size_t)kvn*ND + i*8, pk);
                    cpa16(base + 2*ASEG + r*APITCH + hf*32 + i*8, gvh + kv0n + i*8, true);
                    cpa16(base + 3*ASEG + r*APITCH + hf*32 + i*8, gvl + kv0n + i*8, true);
                }
                CP_COMMIT();
                asm volatile("cp.async.wait_group 1;\n" ::: "memory");
            } else {
                asm volatile("cp.async.wait_group 0;\n" ::: "memory");
            }
            __syncthreads();

            const int kv0 = kvt * 64;
            const uint32_t stg = sbS0 + (uint32_t)(s*4*ASEG*2);
            const uint32_t sKh = stg;
            const uint32_t sKl = stg + ASEG*2;
            const uint32_t sVh = stg + 2*ASEG*2;
            const uint32_t sVl = stg + 3*ASEG*2;

            // ---- S = Q K^T (3-pass split) ----
            float sa[8][4];
            #pragma unroll
            for (int ni = 0; ni < 8; ni++)
                #pragma unroll
                for (int c = 0; c < 4; c++) sa[ni][c] = 0.f;

            #pragma unroll
            for (int ks = 0; ks < 4; ks++) {
                uint32_t bhf[8][2], blf[8][2];
                #pragma unroll
                for (int np = 0; np < 4; np++) {
                    ldsm4(bhf[2*np][0], bhf[2*np][1], bhf[2*np+1][0], bhf[2*np+1][1],
                          sKh + kvb + (uint32_t)(np*16*APITCH*2) + ks*32);
                    ldsm4(blf[2*np][0], blf[2*np][1], blf[2*np+1][0], blf[2*np+1][1],
                          sKl + kvb + (uint32_t)(np*16*APITCH*2) + ks*32);
                }
                #pragma unroll
                for (int ni = 0; ni < 8; ni++)
                    mma16(sa[ni], qfh[ks][0], qfh[ks][1], qfh[ks][2], qfh[ks][3],
                          bhf[ni][0], bhf[ni][1]);
                #pragma unroll
                for (int ni = 0; ni < 8; ni++)
                    mma16(sa[ni], qfl[ks][0], qfl[ks][1], qfl[ks][2], qfl[ks][3],
                          bhf[ni][0], bhf[ni][1]);
                #pragma unroll
                for (int ni = 0; ni < 8; ni++)
                    mma16(sa[ni], qfh[ks][0], qfh[ks][1], qfh[ks][2], qfh[ks][3],
                          blf[ni][0], blf[ni][1]);
            }

            // ---- mask + scale (base-2) ----
            #pragma unroll
            for (int ni = 0; ni < 8; ni++) {
                #pragma unroll
                for (int c = 0; c < 4; c++) {
                    const int qq = qg + ((c >= 2) ? 8 : 0);
                    const int kv = kv0 + ni*8 + 2*t + (c & 1);
                    bool ok;
                    if (hc == 0)      ok = (qq < S_V) && (kv < S_V);
                    else if (hc == 1) ok = (qq >= S_V) && (kv >= S_V) && (qq >= kv);
                    else              ok = (kv < S_V) || (qq >= kv);
                    ok = ok && (kv < NT) && (qq < NT);
                    sa[ni][c] = ok ? sa[ni][c] * SC : -1e30f;
                }
            }

            // ---- online softmax (base-2) ----
            #pragma unroll
            for (int row = 0; row < 2; row++) {
                float rm = -1e30f;
                #pragma unroll
                for (int ni = 0; ni < 8; ni++)
                    rm = fmaxf(rm, fmaxf(sa[ni][row*2], sa[ni][row*2+1]));
                rm = fmaxf(rm, __shfl_xor_sync(0xffffffffu, rm, 1));
                rm = fmaxf(rm, __shfl_xor_sync(0xffffffffu, rm, 2));
                float mnew = fmaxf(m_[row], rm);
                float alpha = exp2f(m_[row] - mnew);
                m_[row] = mnew;
                float psum = 0.f;
                #pragma unroll
                for (int ni = 0; ni < 8; ni++) {
                    float p0 = exp2f(sa[ni][row*2]   - mnew);
                    float p1 = exp2f(sa[ni][row*2+1] - mnew);
                    sa[ni][row*2]   = p0;
                    sa[ni][row*2+1] = p1;
                    psum += p0 + p1;
                }
                psum += __shfl_xor_sync(0xffffffffu, psum, 1);
                psum += __shfl_xor_sync(0xffffffffu, psum, 2);
                l_[row] = l_[row]*alpha + psum;
                #pragma unroll
                for (int ni = 0; ni < 8; ni++) {
                    O[ni][row*2]   *= alpha;
                    O[ni][row*2+1] *= alpha;
                }
            }

            // ---- P -> A fragments (hi/lo) in registers ----
            uint32_t pfh[4][4], pfl[4][4];
            #pragma unroll
            for (int j = 0; j < 4; j++) {
                __nv_bfloat16 h0, l0, h1, l1;
                bf_split(sa[2*j][0], h0, l0); bf_split(sa[2*j][1], h1, l1);
                pfh[j][0] = us2(h0, h1); pfl[j][0] = us2(l0, l1);
                bf_split(sa[2*j][2], h0, l0); bf_split(sa[2*j][3], h1, l1);
                pfh[j][1] = us2(h0, h1); pfl[j][1] = us2(l0, l1);
                bf_split(sa[2*j+1][0], h0, l0); bf_split(sa[2*j+1][1], h1, l1);
                pfh[j][2] = us2(h0, h1); pfl[j][2] = us2(l0, l1);
                bf_split(sa[2*j+1][2], h0, l0); bf_split(sa[2*j+1][3], h1, l1);
                pfh[j][3] = us2(h0, h1); pfl[j][3] = us2(l0, l1);
            }

            // ---- O += P V (3-pass split) ----
            #pragma unroll
            for (int j = 0; j < 4; j++) {
                uint32_t vhf[8][2], vlf[8][2];
                #pragma unroll
                for (int np = 0; np < 4; np++) {
                    ldsm4(vhf[2*np][0], vhf[2*np][1], vhf[2*np+1][0], vhf[2*np+1][1],
                          sVh + kvb + (uint32_t)(np*16*APITCH*2) + j*32);
                    ldsm4(vlf[2*np][0], vlf[2*np][1], vlf[2*np+1][0], vlf[2*np+1][1],
                          sVl + kvb + (uint32_t)(np*16*APITCH*2) + j*32);
                }
                #pragma unroll
                for (int ni = 0; ni < 8; ni++)
                    mma16(O[ni], pfh[j][0], pfh[j][1], pfh[j][2], pfh[j][3],
                          vhf[ni][0], vhf[ni][1]);
                #pragma unroll
                for (int ni = 0; ni < 8; ni++)
                    mma16(O[ni], pfl[j][0], pfl[j][1], pfl[j][2], pfl[j][3],
                          vhf[ni][0], vhf[ni][1]);
                #pragma unroll
                for (int ni = 0; ni < 8; ni++)
                    mma16(O[ni], pfh[j][0], pfh[j][1], pfh[j][2], pfh[j][3],
                          vlf[ni][0], vlf[ni][1]);
            }
            __syncthreads();
        }
    }

    // ---- epilogue: normalize + write bf16 hi/lo (A operand for proj) ----
    #pragma unroll
    for (int row = 0; row < 2; row++) {
        const int q = q0 + w*16 + g + row*8;
        if (q >= NT) continue;
        const float invl = (m_[row] > -5e29f) ? (1.f / l_[row]) : 0.f;
        const size_t base = ((size_t)(b*NT) + q)*NC + h*ND;
        #pragma unroll
        for (int ni = 0; ni < 8; ni++) {
            float x0 = O[ni][row*2]   * invl;
            float x1 = O[ni][row*2+1] * invl;
            __nv_bfloat16 h0, l0, h1, l1;
            bf_split(x0, h0, l0);
            bf_split(x1, h1, l1);
            *(uint32_t*)&g_xh[base + ni*8 + 2*t] = us2(h0, h1);
            *(uint32_t*)&g_xl[base + ni*8 + 2*t] = us2(l0, l1);
        }
    }
}

// ---------------- launch -----------------------------------------------------
extern "C" void kernel_launch(void* const* d_in, const int* in_sizes, int n_in,
                              void* d_out, int out_size) {
    const float* x  = (const float*)d_in[0];
    const float* Wq = (const float*)d_in[1];
    const float* Wk = (const float*)d_in[2];
    const float* Wv = (const float*)d_in[3];
    const float* Wo = (const float*)d_in[4];
    const float* bo = (const float*)d_in[5];
    const int*   sv = (const int*)d_in[6];
    float* out = (float*)d_out;

    cudaFuncSetAttribute((const void*)qkv_kernel,
                         cudaFuncAttributeMaxDynamicSharedMemorySize, SMEM_GEMM);
    cudaFuncSetAttribute((const void*)proj_kernel,
                         cudaFuncAttributeMaxDynamicSharedMemorySize, SMEM_GEMM);
    cudaFuncSetAttribute((const void*)attn_kernel,
                         cudaFuncAttributeMaxDynamicSharedMemorySize, SMEM_ATTN);

    cis_kernel<<<(NT*32 + 255)/256, 256>>>();

    const int cvt_bx = (NM*NC/4 + 255)/256;
    cvt_kernel<<<dim3(cvt_bx, 5), 256>>>(x, Wq, Wk, Wv, Wo);

    qkv_kernel<<<dim3(NC/BN, (NM + BM - 1)/BM, 3), 128, SMEM_GEMM>>>();
    attn_kernel<<<dim3((NT + 63)/64, NH, NB), 128, SMEM_ATTN>>>(sv);
    proj_kernel<<<dim3(NC/BN, (NM + BM - 1)/BM), 128, SMEM_GEMM>>>(bo, out);
}

// round 17
// speedup vs baseline: 1.0474x; 1.0474x over previous
#include <cuda_runtime.h>
#include <cuda_bf16.h>
#include <math.h>
#include <stdint.h>

#define NB 8
#define NT 1221
#define NC 1024
#define NH 16
#define ND 64
#define NM (NB*NT)      // 9768
#define HV 6
#define VTS 12
#define VTP 1280        // padded T for V^T layout (zero padding, 16B aligned rows)

#define BM 128
#define BN 128
#define KTILE 32
#define NKT (NC/KTILE)  // 32
#define PITCH 40        // GEMM smem pitch (bf16) -> conflict-free ldmatrix
#define APITCH 72       // attn smem pitch (bf16) -> conflict-free ldmatrix

// ---------------- scratch (device globals; no allocation allowed) ------------
__device__ float g_cs[NT*32];
__device__ float g_sn[NT*32];
__device__ __nv_bfloat16 g_xh[(size_t)NM*NC];   // A operand hi (X, later attn-out)
__device__ __nv_bfloat16 g_xl[(size_t)NM*NC];   // A operand lo
__device__ __nv_bfloat16 g_wh[4*(size_t)NC*NC]; // Wq,Wk,Wv,Wo hi
__device__ __nv_bfloat16 g_wl[4*(size_t)NC*NC]; // lo
__device__ __nv_bfloat16 g_qh[(size_t)NB*NH*NT*ND];  // Q hi [B,H,T,D]
__device__ __nv_bfloat16 g_ql[(size_t)NB*NH*NT*ND];
__device__ __nv_bfloat16 g_kh[(size_t)NB*NH*NT*ND];  // K hi [B,H,T,D]
__device__ __nv_bfloat16 g_kl[(size_t)NB*NH*NT*ND];
__device__ __nv_bfloat16 g_vth[(size_t)NB*NH*ND*VTP]; // V^T hi [B,H,D,VTP] (pad=0)
__device__ __nv_bfloat16 g_vtl[(size_t)NB*NH*ND*VTP];

// ---------------- helpers ----------------------------------------------------
__device__ __forceinline__ void mma16(float* d,
                                      uint32_t a0, uint32_t a1, uint32_t a2, uint32_t a3,
                                      uint32_t b0, uint32_t b1) {
    asm volatile(
        "mma.sync.aligned.m16n8k16.row.col.f32.bf16.bf16.f32 "
        "{%0,%1,%2,%3},{%4,%5,%6,%7},{%8,%9},{%0,%1,%2,%3};\n"
        : "+f"(d[0]), "+f"(d[1]), "+f"(d[2]), "+f"(d[3])
        : "r"(a0), "r"(a1), "r"(a2), "r"(a3), "r"(b0), "r"(b1));
}
__device__ __forceinline__ void ldsm4(uint32_t& r0, uint32_t& r1, uint32_t& r2, uint32_t& r3,
                                      uint32_t addr) {
    asm volatile("ldmatrix.sync.aligned.m8n8.x4.shared.b16 {%0,%1,%2,%3}, [%4];"
                 : "=r"(r0), "=r"(r1), "=r"(r2), "=r"(r3) : "r"(addr));
}
__device__ __forceinline__ void cpa16(__nv_bfloat16* dst, const __nv_bfloat16* src, bool pred) {
    uint32_t d = (uint32_t)__cvta_generic_to_shared(dst);
    int sz = pred ? 16 : 0;
    asm volatile("cp.async.cg.shared.global [%0], [%1], 16, %2;\n"
                 :: "r"(d), "l"(src), "r"(sz));
}
#define CP_COMMIT() asm volatile("cp.async.commit_group;\n")

__device__ __forceinline__ void bf_split(float x, __nv_bfloat16& h, __nv_bfloat16& l) {
    h = __float2bfloat16(x);
    l = __float2bfloat16(x - __bfloat162float(h));
}
__device__ __forceinline__ uint32_t us2(__nv_bfloat16 a, __nv_bfloat16 b) {
    return (uint32_t)__bfloat16_as_ushort(a) | ((uint32_t)__bfloat16_as_ushort(b) << 16);
}

// GEMM smem layout (bf16 elements)
#define A_ELE (BM*PITCH)
#define B_ELE (BN*PITCH)
#define STAGE_ELE (2*A_ELE + 2*B_ELE)
#define AH_E(s) ((s)*STAGE_ELE)
#define AL_E(s) (AH_E(s) + A_ELE)
#define BH_E(s) (AH_E(s) + 2*A_ELE)
#define BL_E(s) (AH_E(s) + 2*A_ELE + B_ELE)
#define SMEM_GEMM (2*STAGE_ELE*2)   // 81920 B

#define SMEM_ATTN (6*64*APITCH*2)  // 55296 B

// ---------------- rope table -------------------------------------------------
__global__ void cis_kernel() {
    int idx = blockIdx.x*256 + threadIdx.x;
    if (idx >= NT*32) return;
    int t = idx >> 5;
    int i = idx & 31;
    float inv = powf(10000.0f, -((float)(2*i) / 64.0f));
    float ang = (float)t * inv;
    float s, c;
    sincosf(ang, &s, &c);
    g_cs[idx] = c;
    g_sn[idx] = s;
}

// ---------------- fp32 -> (bf16 hi, bf16 lo) conversion ----------------------
__global__ __launch_bounds__(256) void cvt_kernel(
    const float* __restrict__ x,  const float* __restrict__ wq,
    const float* __restrict__ wk, const float* __restrict__ wv,
    const float* __restrict__ wo)
{
    const int seg = blockIdx.y;
    const float* src;
    __nv_bfloat16 *hi, *lo;
    size_t n;
    if (seg == 0) { src = x;  hi = g_xh; lo = g_xl; n = (size_t)NM*NC; }
    else {
        src = (seg==1) ? wq : (seg==2) ? wk : (seg==3) ? wv : wo;
        hi = g_wh + (size_t)(seg-1)*NC*NC;
        lo = g_wl + (size_t)(seg-1)*NC*NC;
        n = (size_t)NC*NC;
    }
    size_t i = ((size_t)blockIdx.x*256 + threadIdx.x) * 4;
    if (i >= n) return;
    float4 v = *(const float4*)(src + i);
    __nv_bfloat16 h0, l0, h1, l1, h2, l2, h3, l3;
    bf_split(v.x, h0, l0); bf_split(v.y, h1, l1);
    bf_split(v.z, h2, l2); bf_split(v.w, h3, l3);
    uint2 hp, lp;
    hp.x = us2(h0, h1); hp.y = us2(h2, h3);
    lp.x = us2(l0, l1); lp.y = us2(l2, l3);
    *(uint2*)(hi + i) = hp;
    *(uint2*)(lo + i) = lp;
}

// ---------------- 3-pass bf16-split GEMM mainloop (mma + ldmatrix) -----------
// 128 threads, 4 warps in 2x2 grid, warp tile 64x64 (6:1 mma:ldsm).
// Single-barrier pipeline: wait -> sync -> prefetch(kt+1) -> compute(kt).
__device__ __forceinline__ void gemm_main(
    const __nv_bfloat16* __restrict__ Ah, const __nv_bfloat16* __restrict__ Al,
    const __nv_bfloat16* __restrict__ Bh, const __nv_bfloat16* __restrict__ Bl,
    int m0, int n0, __nv_bfloat16* sm, float acc[4][8][4])
{
    const int tid  = threadIdx.x;
    const int lane = tid & 31;
    const int warp = tid >> 5;
    const int wm = (warp >> 1) * 64;
    const int wn = (warp & 1) * 64;

    const int lrowA = (lane & 7) + ((lane >> 3) & 1) * 8;
    const int lcolA = ((lane >> 4) & 1) * 8;
    const int lrowB = (lane & 7) + ((lane >> 4) & 1) * 8;
    const int lcolB = ((lane >> 3) & 1) * 8;

    const uint32_t sb = (uint32_t)__cvta_generic_to_shared(sm);

    const bool pa = (m0 + tid) < NM;
    const __nv_bfloat16* arh = Ah + (size_t)(m0 + tid) * NC;
    const __nv_bfloat16* arl = Al + (size_t)(m0 + tid) * NC;
    const __nv_bfloat16* brh = Bh + (size_t)(n0 + tid) * NC;
    const __nv_bfloat16* brl = Bl + (size_t)(n0 + tid) * NC;

    {
        __nv_bfloat16* dah = sm + AH_E(0) + tid*PITCH;
        __nv_bfloat16* dal = sm + AL_E(0) + tid*PITCH;
        __nv_bfloat16* dbh = sm + BH_E(0) + tid*PITCH;
        __nv_bfloat16* dbl = sm + BL_E(0) + tid*PITCH;
        #pragma unroll
        for (int c = 0; c < 4; c++) {
            cpa16(dah + c*8, arh + c*8, pa);
            cpa16(dal + c*8, arl + c*8, pa);
            cpa16(dbh + c*8, brh + c*8, true);
            cpa16(dbl + c*8, brl + c*8, true);
        }
        CP_COMMIT();
    }

    for (int kt = 0; kt < NKT; kt++) {
        const int buf = kt & 1;
        asm volatile("cp.async.wait_group 0;\n" ::: "memory");
        __syncthreads();
        if (kt + 1 < NKT) {
            // prefetch after barrier: buffer buf^1 is free (consumed in kt-1,
            // all readers passed the barrier above)
            const int k0n = (kt + 1) * KTILE;
            const int s2 = buf ^ 1;
            __nv_bfloat16* dah = sm + AH_E(s2) + tid*PITCH;
            __nv_bfloat16* dal = sm + AL_E(s2) + tid*PITCH;
            __nv_bfloat16* dbh = sm + BH_E(s2) + tid*PITCH;
            __nv_bfloat16* dbl = sm + BL_E(s2) + tid*PITCH;
            #pragma unroll
            for (int c = 0; c < 4; c++) {
                cpa16(dah + c*8, arh + k0n + c*8, pa);
                cpa16(dal + c*8, arl + k0n + c*8, pa);
                cpa16(dbh + c*8, brh + k0n + c*8, true);
                cpa16(dbl + c*8, brl + k0n + c*8, true);
            }
            CP_COMMIT();
        }

        const uint32_t aBh = sb + (uint32_t)(AH_E(buf) + (wm + lrowA)*PITCH + lcolA)*2;
        const uint32_t aBl = sb + (uint32_t)(AL_E(buf) + (wm + lrowA)*PITCH + lcolA)*2;
        const uint32_t bBh = sb + (uint32_t)(BH_E(buf) + (wn + lrowB)*PITCH + lcolB)*2;
        const uint32_t bBl = sb + (uint32_t)(BL_E(buf) + (wn + lrowB)*PITCH + lcolB)*2;

        #pragma unroll
        for (int ks = 0; ks < 2; ks++) {
            const uint32_t ko = (uint32_t)(ks*16*2);
            uint32_t ah[4][4], al[4][4], bh[8][2], bl[8][2];
            #pragma unroll
            for (int mi = 0; mi < 4; mi++) {
                ldsm4(ah[mi][0], ah[mi][1], ah[mi][2], ah[mi][3],
                      aBh + (uint32_t)(mi*16*PITCH*2) + ko);
                ldsm4(al[mi][0], al[mi][1], al[mi][2], al[mi][3],
                      aBl + (uint32_t)(mi*16*PITCH*2) + ko);
            }
            #pragma unroll
            for (int np = 0; np < 4; np++) {
                ldsm4(bh[2*np][0], bh[2*np][1], bh[2*np+1][0], bh[2*np+1][1],
                      bBh + (uint32_t)(np*16*PITCH*2) + ko);
                ldsm4(bl[2*np][0], bl[2*np][1], bl[2*np+1][0], bl[2*np+1][1],
                      bBl + (uint32_t)(np*16*PITCH*2) + ko);
            }
            #pragma unroll
            for (int mi = 0; mi < 4; mi++)
                #pragma unroll
                for (int ni = 0; ni < 8; ni++)
                    mma16(acc[mi][ni], ah[mi][0], ah[mi][1], ah[mi][2], ah[mi][3],
                          bh[ni][0], bh[ni][1]);
            #pragma unroll
            for (int mi = 0; mi < 4; mi++)
                #pragma unroll
                for (int ni = 0; ni < 8; ni++)
                    mma16(acc[mi][ni], al[mi][0], al[mi][1], al[mi][2], al[mi][3],
                          bh[ni][0], bh[ni][1]);
            #pragma unroll
            for (int mi = 0; mi < 4; mi++)
                #pragma unroll
                for (int ni = 0; ni < 8; ni++)
                    mma16(acc[mi][ni], ah[mi][0], ah[mi][1], ah[mi][2], ah[mi][3],
                          bl[ni][0], bl[ni][1]);
        }
    }
}

// ---------------- fused QKV GEMM + RoPE + bf16 hi/lo outputs -----------------
__global__ __launch_bounds__(128, 2) void qkv_kernel()
{
    extern __shared__ __nv_bfloat16 sm[];
    const int which = blockIdx.z;
    const __nv_bfloat16* Bh = g_wh + (size_t)which*NC*NC;
    const __nv_bfloat16* Bl = g_wl + (size_t)which*NC*NC;

    const int m0 = blockIdx.y * BM;
    const int n0 = blockIdx.x * BN;

    float acc[4][8][4];
    #pragma unroll
    for (int mi = 0; mi < 4; mi++)
        #pragma unroll
        for (int ni = 0; ni < 8; ni++)
            #pragma unroll
            for (int j = 0; j < 4; j++) acc[mi][ni][j] = 0.f;

    gemm_main(g_xh, g_xl, Bh, Bl, m0, n0, sm, acc);

    const int tid  = threadIdx.x;
    const int lane = tid & 31;
    const int warp = tid >> 5;
    const int wm = (warp >> 1) * 64;
    const int wn = (warp & 1) * 64;
    const int g = lane >> 2;
    const int t = lane & 3;

    #pragma unroll
    for (int mi = 0; mi < 4; mi++) {
        #pragma unroll
        for (int half = 0; half < 2; half++) {
            const int m = m0 + wm + mi*16 + g + half*8;
            if (m >= NM) continue;
            const int bb  = m / NT;
            const int tok = m - bb*NT;
            #pragma unroll
            for (int ni = 0; ni < 8; ni++) {
                const int n = n0 + wn + ni*8 + 2*t;
                const int hh = n >> 6, d = n & 63;
                float e = acc[mi][ni][half*2 + 0];
                float o = acc[mi][ni][half*2 + 1];
                if (which < 2) {
                    float cv = g_cs[tok*32 + (d >> 1)];
                    float sv = g_sn[tok*32 + (d >> 1)];
                    float oe = e*cv - o*sv;
                    float oo = e*sv + o*cv;
                    __nv_bfloat16 he, le, ho, lo2;
                    bf_split(oe, he, le);
                    bf_split(oo, ho, lo2);
                    size_t idx = ((size_t)(bb*NH + hh)*NT + tok)*ND + d;
                    if (which == 0) {
                        *(uint32_t*)&g_qh[idx] = us2(he, ho);
                        *(uint32_t*)&g_ql[idx] = us2(le, lo2);
                    } else {
                        *(uint32_t*)&g_kh[idx] = us2(he, ho);
                        *(uint32_t*)&g_kl[idx] = us2(le, lo2);
                    }
                } else {
                    __nv_bfloat16 he, le, ho, lo2;
                    bf_split(e, he, le);
                    bf_split(o, ho, lo2);
                    size_t rbase = (size_t)(bb*NH + hh)*ND;
                    g_vth[(rbase + d  )*VTP + tok] = he;
                    g_vth[(rbase + d+1)*VTP + tok] = ho;
                    g_vtl[(rbase + d  )*VTP + tok] = le;
                    g_vtl[(rbase + d+1)*VTP + tok] = lo2;
                }
            }
        }
    }
}

// ---------------- output projection: out = AO @ Wo^T + bo --------------------
__global__ __launch_bounds__(128, 2) void proj_kernel(
    const float* __restrict__ bias, float* __restrict__ out)
{
    extern __shared__ __nv_bfloat16 sm[];
    const __nv_bfloat16* Bh = g_wh + (size_t)3*NC*NC;
    const __nv_bfloat16* Bl = g_wl + (size_t)3*NC*NC;

    const int m0 = blockIdx.y * BM;
    const int n0 = blockIdx.x * BN;

    float acc[4][8][4];
    #pragma unroll
    for (int mi = 0; mi < 4; mi++)
        #pragma unroll
        for (int ni = 0; ni < 8; ni++)
            #pragma unroll
            for (int j = 0; j < 4; j++) acc[mi][ni][j] = 0.f;

    gemm_main(g_xh, g_xl, Bh, Bl, m0, n0, sm, acc);

    const int tid  = threadIdx.x;
    const int lane = tid & 31;
    const int warp = tid >> 5;
    const int wm = (warp >> 1) * 64;
    const int wn = (warp & 1) * 64;
    const int g = lane >> 2;
    const int t = lane & 3;

    #pragma unroll
    for (int mi = 0; mi < 4; mi++) {
        #pragma unroll
        for (int half = 0; half < 2; half++) {
            const int m = m0 + wm + mi*16 + g + half*8;
            if (m >= NM) continue;
            #pragma unroll
            for (int ni = 0; ni < 8; ni++) {
                const int n = n0 + wn + ni*8 + 2*t;
                float2 r = make_float2(acc[mi][ni][half*2 + 0] + bias[n],
                                       acc[mi][ni][half*2 + 1] + bias[n+1]);
                *(float2*)&out[(size_t)m*NC + n] = r;
            }
        }
    }
}

// ---------------- tensor-core flash attention with modality mask -------------
__global__ __launch_bounds__(128, 2) void attn_kernel(const int* __restrict__ svp)
{
    extern __shared__ __nv_bfloat16 smb[];
    __nv_bfloat16* sQh = smb;
    __nv_bfloat16* sQl = smb + 64*APITCH;
    __nv_bfloat16* sKh = smb + 2*64*APITCH;
    __nv_bfloat16* sKl = smb + 3*64*APITCH;
    __nv_bfloat16* sVh = smb + 4*64*APITCH;
    __nv_bfloat16* sVl = smb + 5*64*APITCH;

    const int S_V = *svp;
    const int qt = blockIdx.x, h = blockIdx.y, b = blockIdx.z;
    const int hc = (h < HV) ? 0 : ((h < VTS) ? 1 : 2);
    const int q0 = qt * 64;
    const int tid = threadIdx.x, lane = tid & 31, w = tid >> 5;
    const int g = lane >> 2, t = lane & 3;
    const size_t bh = (size_t)(b*NH + h);

    const int lrowA = (lane & 7) + ((lane >> 3) & 1) * 8;
    const int lcolA = ((lane >> 4) & 1) * 8;
    const int lrowB = (lane & 7) + ((lane >> 4) & 1) * 8;
    const int lcolB = ((lane >> 3) & 1) * 8;

    const uint32_t sbQh = (uint32_t)__cvta_generic_to_shared(sQh);
    const uint32_t sbQl = (uint32_t)__cvta_generic_to_shared(sQl);
    const uint32_t sbKh = (uint32_t)__cvta_generic_to_shared(sKh);
    const uint32_t sbKl = (uint32_t)__cvta_generic_to_shared(sKl);
    const uint32_t sbVh = (uint32_t)__cvta_generic_to_shared(sVh);
    const uint32_t sbVl = (uint32_t)__cvta_generic_to_shared(sVl);

    // ---- load Q tile (hi/lo) ----
    {
        int r = tid >> 1, hf = tid & 1;
        int q = q0 + r;
        uint4 z = make_uint4(0,0,0,0);
        const uint4* srh = (const uint4*)&g_qh[(bh*NT + (q < NT ? q : 0))*ND + hf*32];
        const uint4* srl = (const uint4*)&g_ql[(bh*NT + (q < NT ? q : 0))*ND + hf*32];
        #pragma unroll
        for (int i = 0; i < 4; i++) {
            uint4 vh_ = (q < NT) ? srh[i] : z;
            uint4 vl_ = (q < NT) ? srl[i] : z;
            *(uint4*)&sQh[r*APITCH + hf*32 + i*8] = vh_;
            *(uint4*)&sQl[r*APITCH + hf*32 + i*8] = vl_;
        }
    }
    __syncthreads();

    // ---- Q fragments (resident across KV loop) via ldmatrix ----
    uint32_t qfh[4][4], qfl[4][4];
    {
        const uint32_t qb = (uint32_t)(((w*16 + lrowA)*APITCH + lcolA)*2);
        #pragma unroll
        for (int ks = 0; ks < 4; ks++) {
            ldsm4(qfh[ks][0], qfh[ks][1], qfh[ks][2], qfh[ks][3], sbQh + qb + ks*32);
            ldsm4(qfl[ks][0], qfl[ks][1], qfl[ks][2], qfl[ks][3], sbQl + qb + ks*32);
        }
    }

    float O[8][4];
    #pragma unroll
    for (int ni = 0; ni < 8; ni++)
        #pragma unroll
        for (int c = 0; c < 4; c++) O[ni][c] = 0.f;
    float m_[2] = {-1e30f, -1e30f}, l_[2] = {0.f, 0.f};

    const int ceil_sv = (S_V + 63) >> 6;
    int kv_lo = 0, kv_hi = 0;
    if (hc == 0)      { if (q0 < S_V) { kv_lo = 0; kv_hi = ceil_sv; } }
    else if (hc == 1) { if (q0 + 63 >= S_V) { kv_lo = S_V >> 6; kv_hi = qt + 1; } }
    else              { kv_lo = 0; kv_hi = (qt + 1 > ceil_sv) ? (qt + 1) : ceil_sv; }

    const int qg = q0 + w*16 + g;
    const uint32_t kvb = (uint32_t)((lrowB*APITCH + lcolB)*2);

    for (int kvt = kv_lo; kvt < kv_hi; kvt++) {
        const int kv0 = kvt * 64;
        __syncthreads();
        {
            int r = tid >> 1, hf = tid & 1;
            int kv = kv0 + r;
            uint4 z = make_uint4(0,0,0,0);
            const uint4* kh_ = (const uint4*)&g_kh[(bh*NT + (kv < NT ? kv : 0))*ND + hf*32];
            const uint4* kl_ = (const uint4*)&g_kl[(bh*NT + (kv < NT ? kv : 0))*ND + hf*32];
            const uint4* vh_ = (const uint4*)&g_vth[(bh*ND + r)*VTP + kv0 + hf*32];
            const uint4* vl_ = (const uint4*)&g_vtl[(bh*ND + r)*VTP + kv0 + hf*32];
            #pragma unroll
            for (int i = 0; i < 4; i++) {
                uint4 a = (kv < NT) ? kh_[i] : z;
                uint4 c = (kv < NT) ? kl_[i] : z;
                *(uint4*)&sKh[r*APITCH + hf*32 + i*8] = a;
                *(uint4*)&sKl[r*APITCH + hf*32 + i*8] = c;
                uint4 d0 = vh_[i];
                uint4 d1 = vl_[i];
                *(uint4*)&sVh[r*APITCH + hf*32 + i*8] = d0;
                *(uint4*)&sVl[r*APITCH + hf*32 + i*8] = d1;
            }
        }
        __syncthreads();

        // ---- S = Q K^T (3-pass split) ----
        float sa[8][4];
        #pragma unroll
        for (int ni = 0; ni < 8; ni++)
            #pragma unroll
            for (int c = 0; c < 4; c++) sa[ni][c] = 0.f;

        #pragma unroll
        for (int ks = 0; ks < 4; ks++) {
            uint32_t bhf[8][2], blf[8][2];
            #pragma unroll
            for (int np = 0; np < 4; np++) {
                ldsm4(bhf[2*np][0], bhf[2*np][1], bhf[2*np+1][0], bhf[2*np+1][1],
                      sbKh + kvb + (uint32_t)(np*16*APITCH*2) + ks*32);
                ldsm4(blf[2*np][0], blf[2*np][1], blf[2*np+1][0], blf[2*np+1][1],
                      sbKl + kvb + (uint32_t)(np*16*APITCH*2) + ks*32);
            }
            #pragma unroll
            for (int ni = 0; ni < 8; ni++)
                mma16(sa[ni], qfh[ks][0], qfh[ks][1], qfh[ks][2], qfh[ks][3],
                      bhf[ni][0], bhf[ni][1]);
            #pragma unroll
            for (int ni = 0; ni < 8; ni++)
                mma16(sa[ni], qfl[ks][0], qfl[ks][1], qfl[ks][2], qfl[ks][3],
                      bhf[ni][0], bhf[ni][1]);
            #pragma unroll
            for (int ni = 0; ni < 8; ni++)
                mma16(sa[ni], qfh[ks][0], qfh[ks][1], qfh[ks][2], qfh[ks][3],
                      blf[ni][0], blf[ni][1]);
        }

        // ---- mask + scale ----
        #pragma unroll
        for (int ni = 0; ni < 8; ni++) {
            #pragma unroll
            for (int c = 0; c < 4; c++) {
                const int qq = qg + ((c >= 2) ? 8 : 0);
                const int kv = kv0 + ni*8 + 2*t + (c & 1);
                bool ok;
                if (hc == 0)      ok = (qq < S_V) && (kv < S_V);
                else if (hc == 1) ok = (qq >= S_V) && (kv >= S_V) && (qq >= kv);
                else              ok = (kv < S_V) || (qq >= kv);
                ok = ok && (kv < NT) && (qq < NT);
                sa[ni][c] = ok ? sa[ni][c] * 0.125f : -1e30f;
            }
        }

        // ---- online softmax ----
        #pragma unroll
        for (int row = 0; row < 2; row++) {
            float rm = -1e30f;
            #pragma unroll
            for (int ni = 0; ni < 8; ni++)
                rm = fmaxf(rm, fmaxf(sa[ni][row*2], sa[ni][row*2+1]));
            rm = fmaxf(rm, __shfl_xor_sync(0xffffffffu, rm, 1));
            rm = fmaxf(rm, __shfl_xor_sync(0xffffffffu, rm, 2));
            float mnew = fmaxf(m_[row], rm);
            float alpha = __expf(m_[row] - mnew);
            m_[row] = mnew;
            float psum = 0.f;
            #pragma unroll
            for (int ni = 0; ni < 8; ni++) {
                float p0 = __expf(sa[ni][row*2]   - mnew);
                float p1 = __expf(sa[ni][row*2+1] - mnew);
                sa[ni][row*2]   = p0;
                sa[ni][row*2+1] = p1;
                psum += p0 + p1;
            }
            psum += __shfl_xor_sync(0xffffffffu, psum, 1);
            psum += __shfl_xor_sync(0xffffffffu, psum, 2);
            l_[row] = l_[row]*alpha + psum;
            #pragma unroll
            for (int ni = 0; ni < 8; ni++) {
                O[ni][row*2]   *= alpha;
                O[ni][row*2+1] *= alpha;
            }
        }

        // ---- P -> A fragments (hi/lo) in registers ----
        uint32_t pfh[4][4], pfl[4][4];
        #pragma unroll
        for (int j = 0; j < 4; j++) {
            __nv_bfloat16 h0, l0, h1, l1;
            bf_split(sa[2*j][0], h0, l0); bf_split(sa[2*j][1], h1, l1);
            pfh[j][0] = us2(h0, h1); pfl[j][0] = us2(l0, l1);
            bf_split(sa[2*j][2], h0, l0); bf_split(sa[2*j][3], h1, l1);
            pfh[j][1] = us2(h0, h1); pfl[j][1] = us2(l0, l1);
            bf_split(sa[2*j+1][0], h0, l0); bf_split(sa[2*j+1][1], h1, l1);
            pfh[j][2] = us2(h0, h1); pfl[j][2] = us2(l0, l1);
            bf_split(sa[2*j+1][2], h0, l0); bf_split(sa[2*j+1][3], h1, l1);
            pfh[j][3] = us2(h0, h1); pfl[j][3] = us2(l0, l1);
        }

        // ---- O += P V (3-pass split) ----
        #pragma unroll
        for (int j = 0; j < 4; j++) {
            uint32_t vhf[8][2], vlf[8][2];
            #pragma unroll
            for (int np = 0; np < 4; np++) {
                ldsm4(vhf[2*np][0], vhf[2*np][1], vhf[2*np+1][0], vhf[2*np+1][1],
                      sbVh + kvb + (uint32_t)(np*16*APITCH*2) + j*32);
                ldsm4(vlf[2*np][0], vlf[2*np][1], vlf[2*np+1][0], vlf[2*np+1][1],
                      sbVl + kvb + (uint32_t)(np*16*APITCH*2) + j*32);
            }
            #pragma unroll
            for (int ni = 0; ni < 8; ni++)
                mma16(O[ni], pfh[j][0], pfh[j][1], pfh[j][2], pfh[j][3],
                      vhf[ni][0], vhf[ni][1]);
            #pragma unroll
            for (int ni = 0; ni < 8; ni++)
                mma16(O[ni], pfl[j][0], pfl[j][1], pfl[j][2], pfl[j][3],
                      vhf[ni][0], vhf[ni][1]);
            #pragma unroll
            for (int ni = 0; ni < 8; ni++)
                mma16(O[ni], pfh[j][0], pfh[j][1], pfh[j][2], pfh[j][3],
                      vlf[ni][0], vlf[ni][1]);
        }
    }

    // ---- epilogue: normalize + write bf16 hi/lo (A operand for proj) ----
    #pragma unroll
    for (int row = 0; row < 2; row++) {
        const int q = q0 + w*16 + g + row*8;
        if (q >= NT) continue;
        const float invl = (m_[row] > -5e29f) ? (1.f / l_[row]) : 0.f;
        const size_t base = ((size_t)(b*NT) + q)*NC + h*ND;
        #pragma unroll
        for (int ni = 0; ni < 8; ni++) {
            float x0 = O[ni][row*2]   * invl;
            float x1 = O[ni][row*2+1] * invl;
            __nv_bfloat16 h0, l0, h1, l1;
            bf_split(x0, h0, l0);
            bf_split(x1, h1, l1);
            *(uint32_t*)&g_xh[base + ni*8 + 2*t] = us2(h0, h1);
            *(uint32_t*)&g_xl[base + ni*8 + 2*t] = us2(l0, l1);
        }
    }
}

// ---------------- launch -----------------------------------------------------
extern "C" void kernel_launch(void* const* d_in, const int* in_sizes, int n_in,
                              void* d_out, int out_size) {
    const float* x  = (const float*)d_in[0];
    const float* Wq = (const float*)d_in[1];
    const float* Wk = (const float*)d_in[2];
    const float* Wv = (const float*)d_in[3];
    const float* Wo = (const float*)d_in[4];
    const float* bo = (const float*)d_in[5];
    const int*   sv = (const int*)d_in[6];
    float* out = (float*)d_out;

    cudaFuncSetAttribute((const void*)qkv_kernel,
                         cudaFuncAttributeMaxDynamicSharedMemorySize, SMEM_GEMM);
    cudaFuncSetAttribute((const void*)proj_kernel,
                         cudaFuncAttributeMaxDynamicSharedMemorySize, SMEM_GEMM);
    cudaFuncSetAttribute((const void*)attn_kernel,
                         cudaFuncAttributeMaxDynamicSharedMemorySize, SMEM_ATTN);

    cis_kernel<<<(NT*32 + 255)/256, 256>>>();

    const int cvt_bx = (NM*NC/4 + 255)/256;
    cvt_kernel<<<dim3(cvt_bx, 5), 256>>>(x, Wq, Wk, Wv, Wo);

    qkv_kernel<<<dim3(NC/BN, (NM + BM - 1)/BM, 3), 128, SMEM_GEMM>>>();
    attn_kernel<<<dim3((NT + 63)/64, NH, NB), 128, SMEM_ATTN>>>(sv);
    proj_kernel<<<dim3(NC/BN, (NM + BM - 1)/BM), 128, SMEM_GEMM>>>(bo, out);
}